// round 15
// baseline (speedup 1.0000x reference)
#include <cuda_runtime.h>
#include <cuda_fp16.h>
#include <cstdint>

#define BB 2
#define TT 2048
#define EE 1024
#define HH 16
#define DH 64
#define MTOT (BB*TT)   // 4096
#define BHN (BB*HH)    // 32

// ---------------------------------------------------------------------------
// Global scratch. All operands fp16-rounded (error model calibrated R5-R11).
// Q carries 0.125*log2(e) so softmax runs in exp2 domain.
// ---------------------------------------------------------------------------
__device__ __align__(128) __half g_xh[(size_t)MTOT*EE];
__device__ __align__(128) __half g_Wth[(size_t)3*EE*EE];   // [3072][1024]
__device__ __align__(128) __half g_Qh[(size_t)BHN*TT*DH];  // [bh][t][d] (x0.125*log2e)
__device__ __align__(128) __half g_Kh[(size_t)BHN*TT*DH];  // [bh][t][d]
__device__ __align__(128) __half g_Vt[(size_t)BHN*TT*DH];  // [bh][d][t]
__device__ __align__(128) __half g_Ah[(size_t)MTOT*EE];    // attn out
__device__ __align__(128) __half g_Woh[(size_t)EE*EE];     // [out][in]

#define QSCALE 0.18033688011112042f   // 0.125 * log2(e)
#define ONES_H2 0x3C003C00u           // half2(1.0, 1.0)

// ---------------------------------------------------------------------------
// Helpers
// ---------------------------------------------------------------------------
__device__ __forceinline__ uint32_t smem_u32(const void* p) {
  uint32_t a;
  asm("{ .reg .u64 t; cvta.to.shared.u64 t, %1; cvt.u32.u64 %0, t; }" : "=r"(a) : "l"(p));
  return a;
}
__device__ __forceinline__ void ldsm4(uint32_t addr, uint32_t r[4]) {
  asm volatile("ldmatrix.sync.aligned.m8n8.x4.shared.b16 {%0,%1,%2,%3}, [%4];"
               : "=r"(r[0]), "=r"(r[1]), "=r"(r[2]), "=r"(r[3]) : "r"(addr));
}
__device__ __forceinline__ void cp16(uint32_t dst, const void* src) {
  asm volatile("cp.async.ca.shared.global [%0], [%1], 16;" :: "r"(dst), "l"(src) : "memory");
}
__device__ __forceinline__ void cp_commit() {
  asm volatile("cp.async.commit_group;" ::: "memory");
}
template<int N> __device__ __forceinline__ void cp_wait() {
  asm volatile("cp.async.wait_group %0;" :: "n"(N) : "memory");
}
__device__ __forceinline__ float ex2(float x) {
  float r;
  asm("ex2.approx.f32 %0, %1;" : "=f"(r) : "f"(x));
  return r;
}
__device__ __forceinline__ uint32_t pack2(float a, float b) {  // a -> low half
  __half2 h = __floats2half2_rn(a, b);
  return *(uint32_t*)&h;
}
__device__ __forceinline__ uint32_t h2ex2(uint32_t x) {        // 2^x per half
  uint32_t r;
  asm("ex2.approx.f16x2 %0, %1;" : "=r"(r) : "r"(x));
  return r;
}
__device__ __forceinline__ void mma_f16(float c[4], uint32_t a0, uint32_t a1,
                                        uint32_t a2, uint32_t a3,
                                        uint32_t b0, uint32_t b1) {
  asm volatile(
    "mma.sync.aligned.m16n8k16.row.col.f32.f16.f16.f32 "
    "{%0,%1,%2,%3},{%4,%5,%6,%7},{%8,%9},{%0,%1,%2,%3};"
    : "+f"(c[0]), "+f"(c[1]), "+f"(c[2]), "+f"(c[3])
    : "r"(a0), "r"(a1), "r"(a2), "r"(a3), "r"(b0), "r"(b1));
}

// ---------------------------------------------------------------------------
// Fused conversion: x -> g_xh, Wo -> g_Woh in one launch
// ---------------------------------------------------------------------------
#define NX4 (MTOT*EE/4)
#define NW4 (EE*EE/4)
__global__ __launch_bounds__(256) void conv_both(const float* __restrict__ x,
                                                 const float* __restrict__ wo) {
  int i = blockIdx.x * 256 + threadIdx.x;
  const float* s;
  __half* H;
  int j;
  if (i < NX4)            { s = x;  H = g_xh;  j = i; }
  else if (i < NX4 + NW4) { s = wo; H = g_Woh; j = i - NX4; }
  else return;
  float4 v = ((const float4*)s)[j];
  __half2* Hp = (__half2*)(H + (size_t)j*4);
  Hp[0] = __floats2half2_rn(v.x, v.y);
  Hp[1] = __floats2half2_rn(v.z, v.w);
}

// ---------------------------------------------------------------------------
// Weight transpose (QKV): g_Wth[(p*16+h)*64 + d][e] = W_p[h][e][d]
// ---------------------------------------------------------------------------
__global__ __launch_bounds__(256) void transpose_w(
    const float* __restrict__ Wq, const float* __restrict__ Wk,
    const float* __restrict__ Wv) {
  __shared__ float t[32][33];
  const int bz = blockIdx.z;
  const int p = bz >> 4;
  const float* W = (p == 0 ? Wq : p == 1 ? Wk : Wv) + (size_t)(bz & 15) * EE * DH;
  const int e0 = blockIdx.x * 32;
  const int d0 = blockIdx.y * 32;
  const int tx = threadIdx.x, ty = threadIdx.y;
  #pragma unroll
  for (int i = ty; i < 32; i += 8)
    t[i][tx] = W[(size_t)(e0 + i) * DH + d0 + tx];
  __syncthreads();
  #pragma unroll
  for (int i = ty; i < 32; i += 8)
    g_Wth[(size_t)(bz * DH + d0 + i) * EE + e0 + tx] = __float2half_rn(t[tx][i]);
}

// ---------------------------------------------------------------------------
// fp16 GEMM. BM=128 BN=128, BK=64 per stage, 3 stages: the end-of-iter wait is
// cp_wait<1> on a group issued a full iteration earlier -> ~0 exposed latency.
// ---------------------------------------------------------------------------
#define NKIT64 (EE / 64)              // 16
#define G_TILE_H 9216                 // halves per 128x72 tile (64k + 8 pad)
#define G_STAGE_B (2 * G_TILE_H * 2)  // 36864 bytes (A,B)
#define GEMM_SMEM (3 * G_STAGE_B)     // 110592

template<int MODE>
__global__ __launch_bounds__(256, 2) void gemm_f16(
    const __half* __restrict__ pAh, const __half* __restrict__ pBh,
    const float* __restrict__ bias, float* __restrict__ outp) {
  extern __shared__ __align__(16) char gsm[];
  const int tid = threadIdx.x;
  const int lane = tid & 31, q = lane & 3, g = lane >> 2;
  const int wid = tid >> 5, wm = wid >> 2, wn = wid & 3;
  const int n0 = blockIdx.x * 128;
  const size_t m0 = (size_t)blockIdx.y * 128;
  const uint32_t s0 = smem_u32(gsm);

  const int a_row = lane & 15;
  const int a_col = (lane >> 4) << 3;
  const int b_row = (lane & 7) + ((lane >> 4) << 3);
  const int b_col = ((lane >> 3) & 1) << 3;

  float C[4][4][4];
  #pragma unroll
  for (int a = 0; a < 4; a++)
    #pragma unroll
    for (int b = 0; b < 4; b++)
      #pragma unroll
      for (int c = 0; c < 4; c++) C[a][b][c] = 0.f;

  auto issue = [&](int stage, int k0) {
    const uint32_t sb = s0 + (uint32_t)stage * G_STAGE_B;
    #pragma unroll
    for (int t = 0; t < 8; t++) {
      int c = tid + t * 256;                // 0..2047
      int arr = c >> 10, rem = c & 1023;
      int row = rem >> 3, seg = rem & 7;    // 128 rows x 8 segs of 8 halves
      const __half* src = arr ? pBh + (size_t)(n0 + row) * EE + k0 + seg * 8
                              : pAh + (m0 + row) * EE + k0 + seg * 8;
      cp16(sb + (uint32_t)(arr * G_TILE_H + row * 72 + seg * 8) * 2, src);
    }
    cp_commit();
  };

  issue(0, 0);
  issue(1, 64);
  issue(2, 128);
  cp_wait<2>(); __syncthreads();

  for (int i = 0; i < NKIT64; i++) {
    const uint32_t sb = s0 + (uint32_t)(i % 3) * G_STAGE_B;
    const uint32_t tAh = sb, tBh = sb + G_TILE_H*2;
    #pragma unroll
    for (int kc = 0; kc < 4; kc++) {
      const int kc16 = kc * 16;
      uint32_t ah[4][4];
      #pragma unroll
      for (int mt = 0; mt < 4; mt++) {
        const uint32_t off = (uint32_t)(((wm * 64 + mt * 16 + a_row) * 72 + kc16 + a_col) * 2);
        ldsm4(tAh + off, ah[mt]);
      }
      uint32_t bhf[2][4];
      #pragma unroll
      for (int np = 0; np < 2; np++) {
        const uint32_t off = (uint32_t)(((wn * 32 + np * 16 + b_row) * 72 + kc16 + b_col) * 2);
        ldsm4(tBh + off, bhf[np]);
      }
      #pragma unroll
      for (int np = 0; np < 2; np++) {
        #pragma unroll
        for (int j = 0; j < 2; j++) {
          const int nt = np * 2 + j;
          #pragma unroll
          for (int mt = 0; mt < 4; mt++)
            mma_f16(C[mt][nt], ah[mt][0], ah[mt][1], ah[mt][2], ah[mt][3],
                    bhf[np][2*j], bhf[np][2*j+1]);
        }
      }
    }
    if (i + 1 < NKIT64) {
      if (i + 2 < NKIT64) cp_wait<1>(); else cp_wait<0>();
      __syncthreads();
      if (i + 3 < NKIT64) issue(i % 3, (i + 3) * 64);
    }
  }

  // epilogue
  #pragma unroll
  for (int mt = 0; mt < 4; mt++) {
    #pragma unroll
    for (int nt = 0; nt < 4; nt++) {
      #pragma unroll
      for (int e = 0; e < 4; e++) {
        const int r = (int)m0 + wm * 64 + mt * 16 + g + (e >= 2 ? 8 : 0);
        const int c = n0 + wn * 32 + nt * 8 + 2 * q + (e & 1);
        const float v = C[mt][nt][e];
        if (MODE == 0) {
          const int p = c >> 10, rl = c & 1023, hh = rl >> 6, d = rl & 63;
          const int bhi = (r >> 11) * HH + hh, t = r & (TT - 1);
          if (p == 2) {
            g_Vt[((size_t)bhi * DH + d) * TT + t] = __float2half_rn(v);
          } else if (p == 1) {
            g_Kh[((size_t)bhi * TT + t) * DH + d] = __float2half_rn(v);
          } else {
            g_Qh[((size_t)bhi * TT + t) * DH + d] = __float2half_rn(v * QSCALE);
          }
        } else {
          outp[(size_t)r * EE + c] = v + bias[c];
        }
      }
    }
  }
}

// ---------------------------------------------------------------------------
// fp16 flash attention. 128-key stages, 2 stages, one barrier per 128 keys.
// f16x2 exp2 softmax; l-sum via ones-MMA; warp-skip of fully-masked sub-blocks.
// ---------------------------------------------------------------------------
#define AT_Q_H    9216                 // 128*72
#define AT_T_H    4608                 // 64*72
#define AT_ST_H   (4 * AT_T_H)         // K(2x64 rows) + 2x V = 18432 halves
#define ATT_SMEM  ((AT_Q_H + 2 * AT_ST_H) * 2)   // 92160 bytes

__global__ __launch_bounds__(256, 2) void attn_f16() {
  extern __shared__ __align__(16) char asm_[];
  const int tid = threadIdx.x;
  const int lane = tid & 31, q = lane & 3, g = lane >> 2;
  const int wid = tid >> 5;
  const int i0 = ((int)gridDim.x - 1 - (int)blockIdx.x) * 128;  // heavy CTAs first
  const int bh = blockIdx.y;
  const uint32_t s0 = smem_u32(asm_);
  const uint32_t pQh = s0;
  const uint32_t kvBase = s0 + AT_Q_H * 2;

  const int a_row = lane & 15;
  const int a_col = (lane >> 4) << 3;
  const int b_row = (lane & 7) + ((lane >> 4) << 3);
  const int b_col = ((lane >> 3) & 1) << 3;

  // Q (joins KV group 0)
  #pragma unroll
  for (int t = 0; t < 4; t++) {
    int c = tid + t * 256;
    int row = c >> 3, seg = c & 7;
    const __half* src = g_Qh + ((size_t)bh * TT + i0 + row) * DH + seg * 8;
    cp16(pQh + (uint32_t)(row * 72 + seg * 8) * 2, src);
  }
  // Stage layout (halves): K rows 0..127 at 0; V sub0 at 2*AT_T_H; V sub1 at 3*AT_T_H
  auto issue_kv = [&](int stage, int j0) {
    const uint32_t kb = kvBase + (uint32_t)stage * AT_ST_H * 2;
    #pragma unroll
    for (int t = 0; t < 8; t++) {
      int c = tid + t * 256;                // 0..2047
      int arr = c >> 10;                    // 0 = K, 1 = V
      int rem = c & 1023;
      if (arr == 0) {
        int row = rem >> 3, seg = rem & 7;  // 128 key rows
        cp16(kb + (uint32_t)(row * 72 + seg * 8) * 2,
             g_Kh + ((size_t)bh * TT + j0 + row) * DH + seg * 8);
      } else {
        int sub = rem >> 9, rem2 = rem & 511;
        int drow = rem2 >> 3, seg = rem2 & 7;   // 64 d rows x 8 segs
        cp16(kb + (uint32_t)((2 + sub) * AT_T_H + drow * 72 + seg * 8) * 2,
             g_Vt + ((size_t)bh * DH + drow) * TT + j0 + sub * 64 + seg * 8);
      }
    }
    cp_commit();
  };

  const int nb = i0 / 128 + 1;
  issue_kv(0, 0);
  if (nb > 1) { issue_kv(1, 128); cp_wait<1>(); }
  else        cp_wait<0>();
  __syncthreads();

  // Hoist Q fragments (jb-invariant): 4 kc x 4 regs
  uint32_t qf[4][4];
  #pragma unroll
  for (int kc = 0; kc < 4; kc++) {
    const uint32_t qoff = (uint32_t)(((wid * 16 + a_row) * 72 + kc * 16 + a_col) * 2);
    ldsm4(pQh + qoff, qf[kc]);
  }

  float O[8][4];
  #pragma unroll
  for (int a = 0; a < 8; a++)
    #pragma unroll
    for (int e = 0; e < 4; e++) O[a][e] = 0.f;
  float Lacc[4] = {0.f, 0.f, 0.f, 0.f};   // row-sum accumulator (cols identical)
  float m0r = -1e30f, m1r = -1e30f;
  const int row0g = i0 + wid * 16 + g;
  const int row1g = row0g + 8;
  const int rowmax = i0 + wid * 16 + 15;  // warp's last query row

  for (int jb = 0; jb < nb; jb++) {
    const uint32_t kb = kvBase + (uint32_t)(jb & 1) * AT_ST_H * 2;
    #pragma unroll
    for (int sb = 0; sb < 2; sb++) {
      const int j0 = jb * 128 + sb * 64;
      // Warp-uniform skip: sub-block entirely above causal boundary for this
      // warp (P==0, alpha==1 -> exact no-op).
      if (j0 > rowmax) continue;
      const uint32_t tKh = kb + (uint32_t)(sb * 64 * 72) * 2;
      const uint32_t tVh = kb + (uint32_t)((2 + sb) * AT_T_H) * 2;

      // S = Q K^T (log2 domain: scale*log2e folded into Q)
      float S[8][4];
      #pragma unroll
      for (int a = 0; a < 8; a++)
        #pragma unroll
        for (int e = 0; e < 4; e++) S[a][e] = 0.f;
      #pragma unroll
      for (int kc = 0; kc < 4; kc++) {
        const int kc16 = kc * 16;
        #pragma unroll
        for (int np = 0; np < 4; np++) {
          uint32_t kh[4];
          const uint32_t koff = (uint32_t)(((np * 16 + b_row) * 72 + kc16 + b_col) * 2);
          ldsm4(tKh + koff, kh);
          #pragma unroll
          for (int j = 0; j < 2; j++)
            mma_f16(S[np * 2 + j], qf[kc][0], qf[kc][1], qf[kc][2], qf[kc][3],
                    kh[2*j], kh[2*j+1]);
        }
      }

      // causal mask
      if (j0 >= i0) {
        #pragma unroll
        for (int nt = 0; nt < 8; nt++) {
          const int cb = j0 + nt * 8 + 2 * q;
          if (cb     > row0g) S[nt][0] = -1e30f;
          if (cb + 1 > row0g) S[nt][1] = -1e30f;
          if (cb     > row1g) S[nt][2] = -1e30f;
          if (cb + 1 > row1g) S[nt][3] = -1e30f;
        }
      }

      // online max (exp2 domain)
      float mx0 = -1e30f, mx1 = -1e30f;
      #pragma unroll
      for (int nt = 0; nt < 8; nt++) {
        mx0 = fmaxf(mx0, fmaxf(S[nt][0], S[nt][1]));
        mx1 = fmaxf(mx1, fmaxf(S[nt][2], S[nt][3]));
      }
      mx0 = fmaxf(mx0, __shfl_xor_sync(0xffffffffu, mx0, 1));
      mx0 = fmaxf(mx0, __shfl_xor_sync(0xffffffffu, mx0, 2));
      mx1 = fmaxf(mx1, __shfl_xor_sync(0xffffffffu, mx1, 1));
      mx1 = fmaxf(mx1, __shfl_xor_sync(0xffffffffu, mx1, 2));
      const float mn0 = fmaxf(m0r, mx0), mn1 = fmaxf(m1r, mx1);
      const float al0 = ex2(m0r - mn0), al1 = ex2(m1r - mn1);
      m0r = mn0; m1r = mn1;

      // P = 2^(S-mn) computed directly in f16x2 (packed A fragments for PV)
      uint32_t Pp[16];
      #pragma unroll
      for (int nt = 0; nt < 8; nt++) {
        Pp[nt*2]   = h2ex2(pack2(S[nt][0] - mn0, S[nt][1] - mn0));
        Pp[nt*2+1] = h2ex2(pack2(S[nt][2] - mn1, S[nt][3] - mn1));
      }

      // rescale O and L
      #pragma unroll
      for (int nt = 0; nt < 8; nt++) {
        O[nt][0] *= al0; O[nt][1] *= al0;
        O[nt][2] *= al1; O[nt][3] *= al1;
      }
      Lacc[0] *= al0; Lacc[2] *= al1;

      // O += P V ; L += P * ones
      #pragma unroll
      for (int kc = 0; kc < 4; kc++) {
        const uint32_t a0 = Pp[4*kc], a1 = Pp[4*kc+1], a2 = Pp[4*kc+2], a3 = Pp[4*kc+3];
        mma_f16(Lacc, a0, a1, a2, a3, ONES_H2, ONES_H2);
        const int kc16 = kc * 16;
        #pragma unroll
        for (int np = 0; np < 4; np++) {
          uint32_t vh[4];
          const uint32_t voff = (uint32_t)(((np * 16 + b_row) * 72 + kc16 + b_col) * 2);
          ldsm4(tVh + voff, vh);
          #pragma unroll
          for (int j = 0; j < 2; j++)
            mma_f16(O[np * 2 + j], a0, a1, a2, a3, vh[2*j], vh[2*j+1]);
        }
      }
    }
    if (jb + 1 < nb) {
      cp_wait<0>(); __syncthreads();
      if (jb + 2 < nb) issue_kv(jb & 1, (jb + 2) * 128);
    }
  }

  // epilogue (Lacc cols identical -> no shuffle needed)
  const float inv0 = 1.f / Lacc[0], inv1 = 1.f / Lacc[2];
  const int colb = (bh & 15) * DH;
  const size_t orow0 = (size_t)(bh >> 4) * TT + row0g;
  const size_t orow1 = orow0 + 8;
  #pragma unroll
  for (int nd = 0; nd < 8; nd++) {
    const int d0 = nd * 8 + 2 * q;
    __half2* p0 = (__half2*)&g_Ah[orow0 * EE + colb + d0];
    __half2* p1 = (__half2*)&g_Ah[orow1 * EE + colb + d0];
    *p0 = __floats2half2_rn(O[nd][0] * inv0, O[nd][1] * inv0);
    *p1 = __floats2half2_rn(O[nd][2] * inv1, O[nd][3] * inv1);
  }
}

// ---------------------------------------------------------------------------
extern "C" void kernel_launch(void* const* d_in, const int* in_sizes, int n_in,
                              void* d_out, int out_size) {
  const float* x  = (const float*)d_in[0];
  const float* Wq = (const float*)d_in[1];
  const float* Wk = (const float*)d_in[2];
  const float* Wv = (const float*)d_in[3];
  const float* Wo = (const float*)d_in[4];
  const float* wb = (const float*)d_in[5];
  float* out = (float*)d_out;

  __half *xh, *wth, *woh, *ah;
  cudaGetSymbolAddress((void**)&xh, g_xh);
  cudaGetSymbolAddress((void**)&wth, g_Wth);
  cudaGetSymbolAddress((void**)&woh, g_Woh);
  cudaGetSymbolAddress((void**)&ah, g_Ah);

  cudaFuncSetAttribute(gemm_f16<0>, cudaFuncAttributeMaxDynamicSharedMemorySize, GEMM_SMEM);
  cudaFuncSetAttribute(gemm_f16<1>, cudaFuncAttributeMaxDynamicSharedMemorySize, GEMM_SMEM);
  cudaFuncSetAttribute(attn_f16, cudaFuncAttributeMaxDynamicSharedMemorySize, ATT_SMEM);

  conv_both<<<(NX4 + NW4 + 255)/256, 256>>>(x, Wo);
  transpose_w<<<dim3(EE/32, DH/32, 48), dim3(32, 8)>>>(Wq, Wk, Wv);

  gemm_f16<0><<<dim3(3*EE/128, MTOT/128), 256, GEMM_SMEM>>>(xh, wth, nullptr, nullptr);

  attn_f16<<<dim3(TT/128, BHN), 256, ATT_SMEM>>>();

  gemm_f16<1><<<dim3(EE/128, MTOT/128), 256, GEMM_SMEM>>>(ah, woh, wb, out);
}

// round 16
// speedup vs baseline: 1.0423x; 1.0423x over previous
#include <cuda_runtime.h>
#include <cuda_fp16.h>
#include <cstdint>

#define BB 2
#define TT 2048
#define EE 1024
#define HH 16
#define DH 64
#define MTOT (BB*TT)   // 4096
#define BHN (BB*HH)    // 32

// ---------------------------------------------------------------------------
// Global scratch. All operands fp16-rounded (error model calibrated R5-R11).
// Q carries 0.125*log2(e) so softmax runs in exp2 domain.
// ---------------------------------------------------------------------------
__device__ __align__(128) __half g_xh[(size_t)MTOT*EE];
__device__ __align__(128) __half g_Wth[(size_t)3*EE*EE];   // [3072][1024]
__device__ __align__(128) __half g_Qh[(size_t)BHN*TT*DH];  // [bh][t][d] (x0.125*log2e)
__device__ __align__(128) __half g_Kh[(size_t)BHN*TT*DH];  // [bh][t][d]
__device__ __align__(128) __half g_Vt[(size_t)BHN*TT*DH];  // [bh][d][t]
__device__ __align__(128) __half g_Ah[(size_t)MTOT*EE];    // attn out
__device__ __align__(128) __half g_Woh[(size_t)EE*EE];     // [out][in]

#define QSCALE 0.18033688011112042f   // 0.125 * log2(e)
#define ONES_H2 0x3C003C00u           // half2(1.0, 1.0)

// ---------------------------------------------------------------------------
// Helpers
// ---------------------------------------------------------------------------
__device__ __forceinline__ uint32_t smem_u32(const void* p) {
  uint32_t a;
  asm("{ .reg .u64 t; cvta.to.shared.u64 t, %1; cvt.u32.u64 %0, t; }" : "=r"(a) : "l"(p));
  return a;
}
__device__ __forceinline__ void ldsm4(uint32_t addr, uint32_t r[4]) {
  asm volatile("ldmatrix.sync.aligned.m8n8.x4.shared.b16 {%0,%1,%2,%3}, [%4];"
               : "=r"(r[0]), "=r"(r[1]), "=r"(r[2]), "=r"(r[3]) : "r"(addr));
}
__device__ __forceinline__ void cp16(uint32_t dst, const void* src) {
  asm volatile("cp.async.ca.shared.global [%0], [%1], 16;" :: "r"(dst), "l"(src) : "memory");
}
__device__ __forceinline__ void cp_commit() {
  asm volatile("cp.async.commit_group;" ::: "memory");
}
template<int N> __device__ __forceinline__ void cp_wait() {
  asm volatile("cp.async.wait_group %0;" :: "n"(N) : "memory");
}
__device__ __forceinline__ float ex2(float x) {
  float r;
  asm("ex2.approx.f32 %0, %1;" : "=f"(r) : "f"(x));
  return r;
}
__device__ __forceinline__ uint32_t pack2(float a, float b) {  // a -> low half
  __half2 h = __floats2half2_rn(a, b);
  return *(uint32_t*)&h;
}
__device__ __forceinline__ uint32_t h2ex2(uint32_t x) {        // 2^x per half
  uint32_t r;
  asm("ex2.approx.f16x2 %0, %1;" : "=r"(r) : "r"(x));
  return r;
}
__device__ __forceinline__ void mma_f16(float c[4], uint32_t a0, uint32_t a1,
                                        uint32_t a2, uint32_t a3,
                                        uint32_t b0, uint32_t b1) {
  asm volatile(
    "mma.sync.aligned.m16n8k16.row.col.f32.f16.f16.f32 "
    "{%0,%1,%2,%3},{%4,%5,%6,%7},{%8,%9},{%0,%1,%2,%3};"
    : "+f"(c[0]), "+f"(c[1]), "+f"(c[2]), "+f"(c[3])
    : "r"(a0), "r"(a1), "r"(a2), "r"(a3), "r"(b0), "r"(b1));
}

// ---------------------------------------------------------------------------
// Fused conversion: x -> g_xh, Wo -> g_Woh in one launch
// ---------------------------------------------------------------------------
#define NX4 (MTOT*EE/4)
#define NW4 (EE*EE/4)
__global__ __launch_bounds__(256) void conv_both(const float* __restrict__ x,
                                                 const float* __restrict__ wo) {
  int i = blockIdx.x * 256 + threadIdx.x;
  const float* s;
  __half* H;
  int j;
  if (i < NX4)            { s = x;  H = g_xh;  j = i; }
  else if (i < NX4 + NW4) { s = wo; H = g_Woh; j = i - NX4; }
  else return;
  float4 v = ((const float4*)s)[j];
  __half2* Hp = (__half2*)(H + (size_t)j*4);
  Hp[0] = __floats2half2_rn(v.x, v.y);
  Hp[1] = __floats2half2_rn(v.z, v.w);
}

// ---------------------------------------------------------------------------
// Weight transpose (QKV): g_Wth[(p*16+h)*64 + d][e] = W_p[h][e][d]
// ---------------------------------------------------------------------------
__global__ __launch_bounds__(256) void transpose_w(
    const float* __restrict__ Wq, const float* __restrict__ Wk,
    const float* __restrict__ Wv) {
  __shared__ float t[32][33];
  const int bz = blockIdx.z;
  const int p = bz >> 4;
  const float* W = (p == 0 ? Wq : p == 1 ? Wk : Wv) + (size_t)(bz & 15) * EE * DH;
  const int e0 = blockIdx.x * 32;
  const int d0 = blockIdx.y * 32;
  const int tx = threadIdx.x, ty = threadIdx.y;
  #pragma unroll
  for (int i = ty; i < 32; i += 8)
    t[i][tx] = W[(size_t)(e0 + i) * DH + d0 + tx];
  __syncthreads();
  #pragma unroll
  for (int i = ty; i < 32; i += 8)
    g_Wth[(size_t)(bz * DH + d0 + i) * EE + e0 + tx] = __float2half_rn(t[tx][i]);
}

// ---------------------------------------------------------------------------
// fp16 GEMM. BM=128 BN=128, BK=64 per stage, 2 stages (R14 config: verified
// 2 CTAs/SM; the 3-stage variant halved occupancy and regressed in R15).
// ---------------------------------------------------------------------------
#define NKIT64 (EE / 64)              // 16
#define G_TILE_H 9216                 // halves per 128x72 tile (64k + 8 pad)
#define G_STAGE_B (2 * G_TILE_H * 2)  // 36864 bytes (A,B)
#define GEMM_SMEM (2 * G_STAGE_B)     // 73728

template<int MODE>
__global__ __launch_bounds__(256, 2) void gemm_f16(
    const __half* __restrict__ pAh, const __half* __restrict__ pBh,
    const float* __restrict__ bias, float* __restrict__ outp) {
  extern __shared__ __align__(16) char gsm[];
  const int tid = threadIdx.x;
  const int lane = tid & 31, q = lane & 3, g = lane >> 2;
  const int wid = tid >> 5, wm = wid >> 2, wn = wid & 3;
  const int n0 = blockIdx.x * 128;
  const size_t m0 = (size_t)blockIdx.y * 128;
  const uint32_t s0 = smem_u32(gsm);

  const int a_row = lane & 15;
  const int a_col = (lane >> 4) << 3;
  const int b_row = (lane & 7) + ((lane >> 4) << 3);
  const int b_col = ((lane >> 3) & 1) << 3;

  float C[4][4][4];
  #pragma unroll
  for (int a = 0; a < 4; a++)
    #pragma unroll
    for (int b = 0; b < 4; b++)
      #pragma unroll
      for (int c = 0; c < 4; c++) C[a][b][c] = 0.f;

  auto issue = [&](int stage, int k0) {
    const uint32_t sb = s0 + (uint32_t)stage * G_STAGE_B;
    #pragma unroll
    for (int t = 0; t < 8; t++) {
      int c = tid + t * 256;                // 0..2047
      int arr = c >> 10, rem = c & 1023;
      int row = rem >> 3, seg = rem & 7;    // 128 rows x 8 segs of 8 halves
      const __half* src = arr ? pBh + (size_t)(n0 + row) * EE + k0 + seg * 8
                              : pAh + (m0 + row) * EE + k0 + seg * 8;
      cp16(sb + (uint32_t)(arr * G_TILE_H + row * 72 + seg * 8) * 2, src);
    }
    cp_commit();
  };

  issue(0, 0);
  issue(1, 64);
  cp_wait<1>(); __syncthreads();

  for (int i = 0; i < NKIT64; i++) {
    const uint32_t sb = s0 + (uint32_t)(i & 1) * G_STAGE_B;
    const uint32_t tAh = sb, tBh = sb + G_TILE_H*2;
    #pragma unroll
    for (int kc = 0; kc < 4; kc++) {
      const int kc16 = kc * 16;
      uint32_t ah[4][4];
      #pragma unroll
      for (int mt = 0; mt < 4; mt++) {
        const uint32_t off = (uint32_t)(((wm * 64 + mt * 16 + a_row) * 72 + kc16 + a_col) * 2);
        ldsm4(tAh + off, ah[mt]);
      }
      uint32_t bhf[2][4];
      #pragma unroll
      for (int np = 0; np < 2; np++) {
        const uint32_t off = (uint32_t)(((wn * 32 + np * 16 + b_row) * 72 + kc16 + b_col) * 2);
        ldsm4(tBh + off, bhf[np]);
      }
      #pragma unroll
      for (int np = 0; np < 2; np++) {
        #pragma unroll
        for (int j = 0; j < 2; j++) {
          const int nt = np * 2 + j;
          #pragma unroll
          for (int mt = 0; mt < 4; mt++)
            mma_f16(C[mt][nt], ah[mt][0], ah[mt][1], ah[mt][2], ah[mt][3],
                    bhf[np][2*j], bhf[np][2*j+1]);
        }
      }
    }
    if (i + 1 < NKIT64) {
      cp_wait<0>(); __syncthreads();                 // stage i+1 ready, stage i free
      if (i + 2 < NKIT64) issue(i & 1, (i + 2) * 64);
    }
  }

  // epilogue
  #pragma unroll
  for (int mt = 0; mt < 4; mt++) {
    #pragma unroll
    for (int nt = 0; nt < 4; nt++) {
      #pragma unroll
      for (int e = 0; e < 4; e++) {
        const int r = (int)m0 + wm * 64 + mt * 16 + g + (e >= 2 ? 8 : 0);
        const int c = n0 + wn * 32 + nt * 8 + 2 * q + (e & 1);
        const float v = C[mt][nt][e];
        if (MODE == 0) {
          const int p = c >> 10, rl = c & 1023, hh = rl >> 6, d = rl & 63;
          const int bhi = (r >> 11) * HH + hh, t = r & (TT - 1);
          if (p == 2) {
            g_Vt[((size_t)bhi * DH + d) * TT + t] = __float2half_rn(v);
          } else if (p == 1) {
            g_Kh[((size_t)bhi * TT + t) * DH + d] = __float2half_rn(v);
          } else {
            g_Qh[((size_t)bhi * TT + t) * DH + d] = __float2half_rn(v * QSCALE);
          }
        } else {
          outp[(size_t)r * EE + c] = v + bias[c];
        }
      }
    }
  }
}

// ---------------------------------------------------------------------------
// fp16 flash attention. 128-key stages, 2 stages, one barrier per 128 keys.
// f16x2 exp2 softmax; l-sum via ones-MMA; warp-skip of fully-masked sub-blocks.
// ---------------------------------------------------------------------------
#define AT_Q_H    9216                 // 128*72
#define AT_T_H    4608                 // 64*72
#define AT_ST_H   (4 * AT_T_H)         // K(2x64 rows) + 2x V = 18432 halves
#define ATT_SMEM  ((AT_Q_H + 2 * AT_ST_H) * 2)   // 92160 bytes

__global__ __launch_bounds__(256, 2) void attn_f16() {
  extern __shared__ __align__(16) char asm_[];
  const int tid = threadIdx.x;
  const int lane = tid & 31, q = lane & 3, g = lane >> 2;
  const int wid = tid >> 5;
  const int i0 = ((int)gridDim.x - 1 - (int)blockIdx.x) * 128;  // heavy CTAs first
  const int bh = blockIdx.y;
  const uint32_t s0 = smem_u32(asm_);
  const uint32_t pQh = s0;
  const uint32_t kvBase = s0 + AT_Q_H * 2;

  const int a_row = lane & 15;
  const int a_col = (lane >> 4) << 3;
  const int b_row = (lane & 7) + ((lane >> 4) << 3);
  const int b_col = ((lane >> 3) & 1) << 3;

  // Q (joins KV group 0)
  #pragma unroll
  for (int t = 0; t < 4; t++) {
    int c = tid + t * 256;
    int row = c >> 3, seg = c & 7;
    const __half* src = g_Qh + ((size_t)bh * TT + i0 + row) * DH + seg * 8;
    cp16(pQh + (uint32_t)(row * 72 + seg * 8) * 2, src);
  }
  // Stage layout (halves): K rows 0..127 at 0; V sub0 at 2*AT_T_H; V sub1 at 3*AT_T_H
  auto issue_kv = [&](int stage, int j0) {
    const uint32_t kb = kvBase + (uint32_t)stage * AT_ST_H * 2;
    #pragma unroll
    for (int t = 0; t < 8; t++) {
      int c = tid + t * 256;                // 0..2047
      int arr = c >> 10;                    // 0 = K, 1 = V
      int rem = c & 1023;
      if (arr == 0) {
        int row = rem >> 3, seg = rem & 7;  // 128 key rows
        cp16(kb + (uint32_t)(row * 72 + seg * 8) * 2,
             g_Kh + ((size_t)bh * TT + j0 + row) * DH + seg * 8);
      } else {
        int sub = rem >> 9, rem2 = rem & 511;
        int drow = rem2 >> 3, seg = rem2 & 7;   // 64 d rows x 8 segs
        cp16(kb + (uint32_t)((2 + sub) * AT_T_H + drow * 72 + seg * 8) * 2,
             g_Vt + ((size_t)bh * DH + drow) * TT + j0 + sub * 64 + seg * 8);
      }
    }
    cp_commit();
  };

  const int nb = i0 / 128 + 1;
  issue_kv(0, 0);
  if (nb > 1) { issue_kv(1, 128); cp_wait<1>(); }
  else        cp_wait<0>();
  __syncthreads();

  // Hoist Q fragments (jb-invariant): 4 kc x 4 regs
  uint32_t qf[4][4];
  #pragma unroll
  for (int kc = 0; kc < 4; kc++) {
    const uint32_t qoff = (uint32_t)(((wid * 16 + a_row) * 72 + kc * 16 + a_col) * 2);
    ldsm4(pQh + qoff, qf[kc]);
  }

  float O[8][4];
  #pragma unroll
  for (int a = 0; a < 8; a++)
    #pragma unroll
    for (int e = 0; e < 4; e++) O[a][e] = 0.f;
  float Lacc[4] = {0.f, 0.f, 0.f, 0.f};   // row-sum accumulator (cols identical)
  float m0r = -1e30f, m1r = -1e30f;
  const int row0g = i0 + wid * 16 + g;
  const int row1g = row0g + 8;
  const int rowmax = i0 + wid * 16 + 15;  // warp's last query row

  for (int jb = 0; jb < nb; jb++) {
    const uint32_t kb = kvBase + (uint32_t)(jb & 1) * AT_ST_H * 2;
    #pragma unroll
    for (int sb = 0; sb < 2; sb++) {
      const int j0 = jb * 128 + sb * 64;
      // Warp-uniform skip: sub-block entirely above causal boundary (exact no-op)
      if (j0 > rowmax) continue;
      const uint32_t tKh = kb + (uint32_t)(sb * 64 * 72) * 2;
      const uint32_t tVh = kb + (uint32_t)((2 + sb) * AT_T_H) * 2;

      // S = Q K^T (log2 domain: scale*log2e folded into Q)
      float S[8][4];
      #pragma unroll
      for (int a = 0; a < 8; a++)
        #pragma unroll
        for (int e = 0; e < 4; e++) S[a][e] = 0.f;
      #pragma unroll
      for (int kc = 0; kc < 4; kc++) {
        const int kc16 = kc * 16;
        #pragma unroll
        for (int np = 0; np < 4; np++) {
          uint32_t kh[4];
          const uint32_t koff = (uint32_t)(((np * 16 + b_row) * 72 + kc16 + b_col) * 2);
          ldsm4(tKh + koff, kh);
          #pragma unroll
          for (int j = 0; j < 2; j++)
            mma_f16(S[np * 2 + j], qf[kc][0], qf[kc][1], qf[kc][2], qf[kc][3],
                    kh[2*j], kh[2*j+1]);
        }
      }

      // causal mask
      if (j0 >= i0) {
        #pragma unroll
        for (int nt = 0; nt < 8; nt++) {
          const int cb = j0 + nt * 8 + 2 * q;
          if (cb     > row0g) S[nt][0] = -1e30f;
          if (cb + 1 > row0g) S[nt][1] = -1e30f;
          if (cb     > row1g) S[nt][2] = -1e30f;
          if (cb + 1 > row1g) S[nt][3] = -1e30f;
        }
      }

      // online max (exp2 domain)
      float mx0 = -1e30f, mx1 = -1e30f;
      #pragma unroll
      for (int nt = 0; nt < 8; nt++) {
        mx0 = fmaxf(mx0, fmaxf(S[nt][0], S[nt][1]));
        mx1 = fmaxf(mx1, fmaxf(S[nt][2], S[nt][3]));
      }
      mx0 = fmaxf(mx0, __shfl_xor_sync(0xffffffffu, mx0, 1));
      mx0 = fmaxf(mx0, __shfl_xor_sync(0xffffffffu, mx0, 2));
      mx1 = fmaxf(mx1, __shfl_xor_sync(0xffffffffu, mx1, 1));
      mx1 = fmaxf(mx1, __shfl_xor_sync(0xffffffffu, mx1, 2));
      const float mn0 = fmaxf(m0r, mx0), mn1 = fmaxf(m1r, mx1);
      const float al0 = ex2(m0r - mn0), al1 = ex2(m1r - mn1);
      m0r = mn0; m1r = mn1;

      // P = 2^(S-mn) computed directly in f16x2 (packed A fragments for PV)
      uint32_t Pp[16];
      #pragma unroll
      for (int nt = 0; nt < 8; nt++) {
        Pp[nt*2]   = h2ex2(pack2(S[nt][0] - mn0, S[nt][1] - mn0));
        Pp[nt*2+1] = h2ex2(pack2(S[nt][2] - mn1, S[nt][3] - mn1));
      }

      // rescale O and L
      #pragma unroll
      for (int nt = 0; nt < 8; nt++) {
        O[nt][0] *= al0; O[nt][1] *= al0;
        O[nt][2] *= al1; O[nt][3] *= al1;
      }
      Lacc[0] *= al0; Lacc[2] *= al1;

      // O += P V ; L += P * ones
      #pragma unroll
      for (int kc = 0; kc < 4; kc++) {
        const uint32_t a0 = Pp[4*kc], a1 = Pp[4*kc+1], a2 = Pp[4*kc+2], a3 = Pp[4*kc+3];
        mma_f16(Lacc, a0, a1, a2, a3, ONES_H2, ONES_H2);
        const int kc16 = kc * 16;
        #pragma unroll
        for (int np = 0; np < 4; np++) {
          uint32_t vh[4];
          const uint32_t voff = (uint32_t)(((np * 16 + b_row) * 72 + kc16 + b_col) * 2);
          ldsm4(tVh + voff, vh);
          #pragma unroll
          for (int j = 0; j < 2; j++)
            mma_f16(O[np * 2 + j], a0, a1, a2, a3, vh[2*j], vh[2*j+1]);
        }
      }
    }
    if (jb + 1 < nb) {
      cp_wait<0>(); __syncthreads();
      if (jb + 2 < nb) issue_kv(jb & 1, (jb + 2) * 128);
    }
  }

  // epilogue (Lacc cols identical -> no shuffle needed)
  const float inv0 = 1.f / Lacc[0], inv1 = 1.f / Lacc[2];
  const int colb = (bh & 15) * DH;
  const size_t orow0 = (size_t)(bh >> 4) * TT + row0g;
  const size_t orow1 = orow0 + 8;
  #pragma unroll
  for (int nd = 0; nd < 8; nd++) {
    const int d0 = nd * 8 + 2 * q;
    __half2* p0 = (__half2*)&g_Ah[orow0 * EE + colb + d0];
    __half2* p1 = (__half2*)&g_Ah[orow1 * EE + colb + d0];
    *p0 = __floats2half2_rn(O[nd][0] * inv0, O[nd][1] * inv0);
    *p1 = __floats2half2_rn(O[nd][2] * inv1, O[nd][3] * inv1);
  }
}

// ---------------------------------------------------------------------------
extern "C" void kernel_launch(void* const* d_in, const int* in_sizes, int n_in,
                              void* d_out, int out_size) {
  const float* x  = (const float*)d_in[0];
  const float* Wq = (const float*)d_in[1];
  const float* Wk = (const float*)d_in[2];
  const float* Wv = (const float*)d_in[3];
  const float* Wo = (const float*)d_in[4];
  const float* wb = (const float*)d_in[5];
  float* out = (float*)d_out;

  __half *xh, *wth, *woh, *ah;
  cudaGetSymbolAddress((void**)&xh, g_xh);
  cudaGetSymbolAddress((void**)&wth, g_Wth);
  cudaGetSymbolAddress((void**)&woh, g_Woh);
  cudaGetSymbolAddress((void**)&ah, g_Ah);

  cudaFuncSetAttribute(gemm_f16<0>, cudaFuncAttributeMaxDynamicSharedMemorySize, GEMM_SMEM);
  cudaFuncSetAttribute(gemm_f16<1>, cudaFuncAttributeMaxDynamicSharedMemorySize, GEMM_SMEM);
  cudaFuncSetAttribute(attn_f16, cudaFuncAttributeMaxDynamicSharedMemorySize, ATT_SMEM);

  conv_both<<<(NX4 + NW4 + 255)/256, 256>>>(x, Wo);
  transpose_w<<<dim3(EE/32, DH/32, 48), dim3(32, 8)>>>(Wq, Wk, Wv);

  gemm_f16<0><<<dim3(3*EE/128, MTOT/128), 256, GEMM_SMEM>>>(xh, wth, nullptr, nullptr);

  attn_f16<<<dim3(TT/128, BHN), 256, ATT_SMEM>>>();

  gemm_f16<1><<<dim3(EE/128, MTOT/128), 256, GEMM_SMEM>>>(ah, woh, wb, out);
}

// round 17
// speedup vs baseline: 1.1068x; 1.0619x over previous
#include <cuda_runtime.h>
#include <cuda_fp16.h>
#include <cstdint>

#define BB 2
#define TT 2048
#define EE 1024
#define HH 16
#define DH 64
#define MTOT (BB*TT)   // 4096
#define BHN (BB*HH)    // 32

// ---------------------------------------------------------------------------
// Global scratch. All operands fp16-rounded (error model calibrated R5-R11).
// Q carries 0.125*log2(e) so softmax runs in exp2 domain.
// ---------------------------------------------------------------------------
__device__ __align__(128) __half g_xh[(size_t)MTOT*EE];
__device__ __align__(128) __half g_Wth[(size_t)3*EE*EE];   // [3072][1024]
__device__ __align__(128) __half g_Qh[(size_t)BHN*TT*DH];  // [bh][t][d] (x0.125*log2e)
__device__ __align__(128) __half g_Kh[(size_t)BHN*TT*DH];  // [bh][t][d]
__device__ __align__(128) __half g_Vt[(size_t)BHN*TT*DH];  // [bh][d][t]
__device__ __align__(128) __half g_Ah[(size_t)MTOT*EE];    // attn out
__device__ __align__(128) __half g_Woh[(size_t)EE*EE];     // [out][in]

#define QSCALE 0.18033688011112042f   // 0.125 * log2(e)
#define ONES_H2 0x3C003C00u           // half2(1.0, 1.0)

// ---------------------------------------------------------------------------
// Helpers
// ---------------------------------------------------------------------------
__device__ __forceinline__ uint32_t smem_u32(const void* p) {
  uint32_t a;
  asm("{ .reg .u64 t; cvta.to.shared.u64 t, %1; cvt.u32.u64 %0, t; }" : "=r"(a) : "l"(p));
  return a;
}
__device__ __forceinline__ void ldsm4(uint32_t addr, uint32_t r[4]) {
  asm volatile("ldmatrix.sync.aligned.m8n8.x4.shared.b16 {%0,%1,%2,%3}, [%4];"
               : "=r"(r[0]), "=r"(r[1]), "=r"(r[2]), "=r"(r[3]) : "r"(addr));
}
__device__ __forceinline__ void cp16(uint32_t dst, const void* src) {
  asm volatile("cp.async.ca.shared.global [%0], [%1], 16;" :: "r"(dst), "l"(src) : "memory");
}
__device__ __forceinline__ void cp_commit() {
  asm volatile("cp.async.commit_group;" ::: "memory");
}
template<int N> __device__ __forceinline__ void cp_wait() {
  asm volatile("cp.async.wait_group %0;" :: "n"(N) : "memory");
}
__device__ __forceinline__ float ex2(float x) {
  float r;
  asm("ex2.approx.f32 %0, %1;" : "=f"(r) : "f"(x));
  return r;
}
__device__ __forceinline__ uint32_t pack2(float a, float b) {  // a -> low half
  __half2 h = __floats2half2_rn(a, b);
  return *(uint32_t*)&h;
}
__device__ __forceinline__ uint32_t h2ex2(uint32_t x) {        // 2^x per half
  uint32_t r;
  asm("ex2.approx.f16x2 %0, %1;" : "=r"(r) : "r"(x));
  return r;
}
__device__ __forceinline__ void mma_f16(float c[4], uint32_t a0, uint32_t a1,
                                        uint32_t a2, uint32_t a3,
                                        uint32_t b0, uint32_t b1) {
  asm volatile(
    "mma.sync.aligned.m16n8k16.row.col.f32.f16.f16.f32 "
    "{%0,%1,%2,%3},{%4,%5,%6,%7},{%8,%9},{%0,%1,%2,%3};"
    : "+f"(c[0]), "+f"(c[1]), "+f"(c[2]), "+f"(c[3])
    : "r"(a0), "r"(a1), "r"(a2), "r"(a3), "r"(b0), "r"(b1));
}

// ---------------------------------------------------------------------------
// Fused prep: x -> g_xh, Wo -> g_Woh, and W transpose, all in one launch.
// Block ranges: [0, NB_X) x-conv, [NB_X, NB_CONV) wo-conv,
//               [NB_CONV, NB_CONV+3072) transpose.
// ---------------------------------------------------------------------------
#define NX4 (MTOT*EE/4)
#define NW4 (EE*EE/4)
#define NB_X   (NX4 / 256)            // 4096
#define NB_CONV (NB_X + NW4 / 256)    // 5120
#define NB_PREP (NB_CONV + 3072)

__global__ __launch_bounds__(256) void prep_all(
    const float* __restrict__ x, const float* __restrict__ wo,
    const float* __restrict__ Wq, const float* __restrict__ Wk,
    const float* __restrict__ Wv) {
  __shared__ float t[32][33];
  const int bi = blockIdx.x;
  const int tid = threadIdx.x;
  if (bi < NB_CONV) {
    const float* s;
    __half* H;
    int j;
    if (bi < NB_X) { s = x;  H = g_xh;  j = bi * 256 + tid; }
    else           { s = wo; H = g_Woh; j = (bi - NB_X) * 256 + tid; }
    float4 v = ((const float4*)s)[j];
    __half2* Hp = (__half2*)(H + (size_t)j*4);
    Hp[0] = __floats2half2_rn(v.x, v.y);
    Hp[1] = __floats2half2_rn(v.z, v.w);
  } else {
    const int bi2 = bi - NB_CONV;
    const int ex = bi2 & 31;            // e0 block (EE/32 = 32)
    const int dy = (bi2 >> 5) & 1;      // d0 block (DH/32 = 2)
    const int bz = bi2 >> 6;            // 0..47 = p*16+h
    const int p = bz >> 4;
    const float* W = (p == 0 ? Wq : p == 1 ? Wk : Wv) + (size_t)(bz & 15) * EE * DH;
    const int e0 = ex * 32;
    const int d0 = dy * 32;
    const int tx = tid & 31, ty = tid >> 5;
    #pragma unroll
    for (int i = ty; i < 32; i += 8)
      t[i][tx] = W[(size_t)(e0 + i) * DH + d0 + tx];
    __syncthreads();
    #pragma unroll
    for (int i = ty; i < 32; i += 8)
      g_Wth[(size_t)(bz * DH + d0 + i) * EE + e0 + tx] = __float2half_rn(t[tx][i]);
  }
}

// ---------------------------------------------------------------------------
// fp16 GEMM. BM=128 BN=128, BK=64 per stage, 2 stages (verified 2 CTAs/SM).
// MODE 0 V-region CTAs transpose through smem for coalesced [d][t] stores.
// ---------------------------------------------------------------------------
#define NKIT64 (EE / 64)              // 16
#define G_TILE_H 9216                 // halves per 128x72 tile (64k + 8 pad)
#define G_STAGE_B (2 * G_TILE_H * 2)  // 36864 bytes (A,B)
#define GEMM_SMEM (2 * G_STAGE_B)     // 73728

template<int MODE>
__global__ __launch_bounds__(256, 2) void gemm_f16(
    const __half* __restrict__ pAh, const __half* __restrict__ pBh,
    const float* __restrict__ bias, float* __restrict__ outp) {
  extern __shared__ __align__(16) char gsm[];
  const int tid = threadIdx.x;
  const int lane = tid & 31, q = lane & 3, g = lane >> 2;
  const int wid = tid >> 5, wm = wid >> 2, wn = wid & 3;
  const int n0 = blockIdx.x * 128;
  const size_t m0 = (size_t)blockIdx.y * 128;
  const uint32_t s0 = smem_u32(gsm);

  const int a_row = lane & 15;
  const int a_col = (lane >> 4) << 3;
  const int b_row = (lane & 7) + ((lane >> 4) << 3);
  const int b_col = ((lane >> 3) & 1) << 3;

  float C[4][4][4];
  #pragma unroll
  for (int a = 0; a < 4; a++)
    #pragma unroll
    for (int b = 0; b < 4; b++)
      #pragma unroll
      for (int c = 0; c < 4; c++) C[a][b][c] = 0.f;

  auto issue = [&](int stage, int k0) {
    const uint32_t sb = s0 + (uint32_t)stage * G_STAGE_B;
    #pragma unroll
    for (int t = 0; t < 8; t++) {
      int c = tid + t * 256;                // 0..2047
      int arr = c >> 10, rem = c & 1023;
      int row = rem >> 3, seg = rem & 7;    // 128 rows x 8 segs of 8 halves
      const __half* src = arr ? pBh + (size_t)(n0 + row) * EE + k0 + seg * 8
                              : pAh + (m0 + row) * EE + k0 + seg * 8;
      cp16(sb + (uint32_t)(arr * G_TILE_H + row * 72 + seg * 8) * 2, src);
    }
    cp_commit();
  };

  issue(0, 0);
  issue(1, 64);
  cp_wait<1>(); __syncthreads();

  for (int i = 0; i < NKIT64; i++) {
    const uint32_t sb = s0 + (uint32_t)(i & 1) * G_STAGE_B;
    const uint32_t tAh = sb, tBh = sb + G_TILE_H*2;
    #pragma unroll
    for (int kc = 0; kc < 4; kc++) {
      const int kc16 = kc * 16;
      uint32_t ah[4][4];
      #pragma unroll
      for (int mt = 0; mt < 4; mt++) {
        const uint32_t off = (uint32_t)(((wm * 64 + mt * 16 + a_row) * 72 + kc16 + a_col) * 2);
        ldsm4(tAh + off, ah[mt]);
      }
      uint32_t bhf[2][4];
      #pragma unroll
      for (int np = 0; np < 2; np++) {
        const uint32_t off = (uint32_t)(((wn * 32 + np * 16 + b_row) * 72 + kc16 + b_col) * 2);
        ldsm4(tBh + off, bhf[np]);
      }
      #pragma unroll
      for (int np = 0; np < 2; np++) {
        #pragma unroll
        for (int j = 0; j < 2; j++) {
          const int nt = np * 2 + j;
          #pragma unroll
          for (int mt = 0; mt < 4; mt++)
            mma_f16(C[mt][nt], ah[mt][0], ah[mt][1], ah[mt][2], ah[mt][3],
                    bhf[np][2*j], bhf[np][2*j+1]);
        }
      }
    }
    if (i + 1 < NKIT64) {
      cp_wait<0>(); __syncthreads();                 // stage i+1 ready, stage i free
      if (i + 2 < NKIT64) issue(i & 1, (i + 2) * 64);
    }
  }

  // epilogue
  if (MODE == 0 && (n0 >> 10) == 2) {
    // V region: transpose through smem so global stores are coalesced rows of
    // g_Vt[bh][d][t]. p is CTA-uniform (128-col blocks never straddle the
    // 1024-col projection boundary); m-blocks never straddle batches.
    __syncthreads();                       // pipeline smem now safe to reuse
    __half* st = (__half*)gsm;             // [128 dl][136 row] halves
    #pragma unroll
    for (int mt = 0; mt < 4; mt++) {
      #pragma unroll
      for (int nt = 0; nt < 4; nt++) {
        #pragma unroll
        for (int e = 0; e < 4; e++) {
          const int row = wm * 64 + mt * 16 + g + (e >= 2 ? 8 : 0);
          const int dl = wn * 32 + nt * 8 + 2 * q + (e & 1);
          st[dl * 136 + row] = __float2half_rn(C[mt][nt][e]);
        }
      }
    }
    __syncthreads();
    const int batch = (int)(m0 >> 11);
    const int t0 = (int)(m0 & (TT - 1));
    const int rlb = n0 & 1023;
    #pragma unroll
    for (int idx = tid; idx < 2048; idx += 256) {   // 128 dl x 16 float4 segs
      const int dl = idx >> 4, seg = idx & 15;
      const int rl = rlb + dl, hh = rl >> 6, d = rl & 63;
      const float4 val = *(const float4*)(st + dl * 136 + seg * 8);
      *(float4*)(g_Vt + ((size_t)(batch * HH + hh) * DH + d) * TT + t0 + seg * 8) = val;
    }
  } else {
    #pragma unroll
    for (int mt = 0; mt < 4; mt++) {
      #pragma unroll
      for (int nt = 0; nt < 4; nt++) {
        #pragma unroll
        for (int e = 0; e < 4; e++) {
          const int r = (int)m0 + wm * 64 + mt * 16 + g + (e >= 2 ? 8 : 0);
          const int c = n0 + wn * 32 + nt * 8 + 2 * q + (e & 1);
          const float v = C[mt][nt][e];
          if (MODE == 0) {
            const int rl = c & 1023, hh = rl >> 6, d = rl & 63;
            const int bhi = (r >> 11) * HH + hh, t = r & (TT - 1);
            if ((c >> 10) == 1) {
              g_Kh[((size_t)bhi * TT + t) * DH + d] = __float2half_rn(v);
            } else {
              g_Qh[((size_t)bhi * TT + t) * DH + d] = __float2half_rn(v * QSCALE);
            }
          } else {
            outp[(size_t)r * EE + c] = v + bias[c];
          }
        }
      }
    }
  }
}

// ---------------------------------------------------------------------------
// fp16 flash attention. 128-key stages, 2 stages, one barrier per 128 keys.
// f16x2 exp2 softmax; l-sum via ones-MMA; warp-skip of fully-masked sub-blocks.
// ---------------------------------------------------------------------------
#define AT_Q_H    9216                 // 128*72
#define AT_T_H    4608                 // 64*72
#define AT_ST_H   (4 * AT_T_H)         // K(2x64 rows) + 2x V = 18432 halves
#define ATT_SMEM  ((AT_Q_H + 2 * AT_ST_H) * 2)   // 92160 bytes

__global__ __launch_bounds__(256, 2) void attn_f16() {
  extern __shared__ __align__(16) char asm_[];
  const int tid = threadIdx.x;
  const int lane = tid & 31, q = lane & 3, g = lane >> 2;
  const int wid = tid >> 5;
  const int i0 = ((int)gridDim.x - 1 - (int)blockIdx.x) * 128;  // heavy CTAs first
  const int bh = blockIdx.y;
  const uint32_t s0 = smem_u32(asm_);
  const uint32_t pQh = s0;
  const uint32_t kvBase = s0 + AT_Q_H * 2;

  const int a_row = lane & 15;
  const int a_col = (lane >> 4) << 3;
  const int b_row = (lane & 7) + ((lane >> 4) << 3);
  const int b_col = ((lane >> 3) & 1) << 3;

  // Q (joins KV group 0)
  #pragma unroll
  for (int t = 0; t < 4; t++) {
    int c = tid + t * 256;
    int row = c >> 3, seg = c & 7;
    const __half* src = g_Qh + ((size_t)bh * TT + i0 + row) * DH + seg * 8;
    cp16(pQh + (uint32_t)(row * 72 + seg * 8) * 2, src);
  }
  // Stage layout (halves): K rows 0..127 at 0; V sub0 at 2*AT_T_H; V sub1 at 3*AT_T_H
  auto issue_kv = [&](int stage, int j0) {
    const uint32_t kb = kvBase + (uint32_t)stage * AT_ST_H * 2;
    #pragma unroll
    for (int t = 0; t < 8; t++) {
      int c = tid + t * 256;                // 0..2047
      int arr = c >> 10;                    // 0 = K, 1 = V
      int rem = c & 1023;
      if (arr == 0) {
        int row = rem >> 3, seg = rem & 7;  // 128 key rows
        cp16(kb + (uint32_t)(row * 72 + seg * 8) * 2,
             g_Kh + ((size_t)bh * TT + j0 + row) * DH + seg * 8);
      } else {
        int sub = rem >> 9, rem2 = rem & 511;
        int drow = rem2 >> 3, seg = rem2 & 7;   // 64 d rows x 8 segs
        cp16(kb + (uint32_t)((2 + sub) * AT_T_H + drow * 72 + seg * 8) * 2,
             g_Vt + ((size_t)bh * DH + drow) * TT + j0 + sub * 64 + seg * 8);
      }
    }
    cp_commit();
  };

  const int nb = i0 / 128 + 1;
  issue_kv(0, 0);
  if (nb > 1) { issue_kv(1, 128); cp_wait<1>(); }
  else        cp_wait<0>();
  __syncthreads();

  // Hoist Q fragments (jb-invariant): 4 kc x 4 regs
  uint32_t qf[4][4];
  #pragma unroll
  for (int kc = 0; kc < 4; kc++) {
    const uint32_t qoff = (uint32_t)(((wid * 16 + a_row) * 72 + kc * 16 + a_col) * 2);
    ldsm4(pQh + qoff, qf[kc]);
  }

  float O[8][4];
  #pragma unroll
  for (int a = 0; a < 8; a++)
    #pragma unroll
    for (int e = 0; e < 4; e++) O[a][e] = 0.f;
  float Lacc[4] = {0.f, 0.f, 0.f, 0.f};   // row-sum accumulator (cols identical)
  float m0r = -1e30f, m1r = -1e30f;
  const int row0g = i0 + wid * 16 + g;
  const int row1g = row0g + 8;
  const int rowmax = i0 + wid * 16 + 15;  // warp's last query row

  for (int jb = 0; jb < nb; jb++) {
    const uint32_t kb = kvBase + (uint32_t)(jb & 1) * AT_ST_H * 2;
    #pragma unroll
    for (int sb = 0; sb < 2; sb++) {
      const int j0 = jb * 128 + sb * 64;
      // Warp-uniform skip: sub-block entirely above causal boundary (exact no-op)
      if (j0 > rowmax) continue;
      const uint32_t tKh = kb + (uint32_t)(sb * 64 * 72) * 2;
      const uint32_t tVh = kb + (uint32_t)((2 + sb) * AT_T_H) * 2;

      // S = Q K^T (log2 domain: scale*log2e folded into Q)
      float S[8][4];
      #pragma unroll
      for (int a = 0; a < 8; a++)
        #pragma unroll
        for (int e = 0; e < 4; e++) S[a][e] = 0.f;
      #pragma unroll
      for (int kc = 0; kc < 4; kc++) {
        const int kc16 = kc * 16;
        #pragma unroll
        for (int np = 0; np < 4; np++) {
          uint32_t kh[4];
          const uint32_t koff = (uint32_t)(((np * 16 + b_row) * 72 + kc16 + b_col) * 2);
          ldsm4(tKh + koff, kh);
          #pragma unroll
          for (int j = 0; j < 2; j++)
            mma_f16(S[np * 2 + j], qf[kc][0], qf[kc][1], qf[kc][2], qf[kc][3],
                    kh[2*j], kh[2*j+1]);
        }
      }

      // causal mask
      if (j0 >= i0) {
        #pragma unroll
        for (int nt = 0; nt < 8; nt++) {
          const int cb = j0 + nt * 8 + 2 * q;
          if (cb     > row0g) S[nt][0] = -1e30f;
          if (cb + 1 > row0g) S[nt][1] = -1e30f;
          if (cb     > row1g) S[nt][2] = -1e30f;
          if (cb + 1 > row1g) S[nt][3] = -1e30f;
        }
      }

      // online max (exp2 domain)
      float mx0 = -1e30f, mx1 = -1e30f;
      #pragma unroll
      for (int nt = 0; nt < 8; nt++) {
        mx0 = fmaxf(mx0, fmaxf(S[nt][0], S[nt][1]));
        mx1 = fmaxf(mx1, fmaxf(S[nt][2], S[nt][3]));
      }
      mx0 = fmaxf(mx0, __shfl_xor_sync(0xffffffffu, mx0, 1));
      mx0 = fmaxf(mx0, __shfl_xor_sync(0xffffffffu, mx0, 2));
      mx1 = fmaxf(mx1, __shfl_xor_sync(0xffffffffu, mx1, 1));
      mx1 = fmaxf(mx1, __shfl_xor_sync(0xffffffffu, mx1, 2));
      const float mn0 = fmaxf(m0r, mx0), mn1 = fmaxf(m1r, mx1);
      const float al0 = ex2(m0r - mn0), al1 = ex2(m1r - mn1);
      m0r = mn0; m1r = mn1;

      // P = 2^(S-mn) computed directly in f16x2 (packed A fragments for PV)
      uint32_t Pp[16];
      #pragma unroll
      for (int nt = 0; nt < 8; nt++) {
        Pp[nt*2]   = h2ex2(pack2(S[nt][0] - mn0, S[nt][1] - mn0));
        Pp[nt*2+1] = h2ex2(pack2(S[nt][2] - mn1, S[nt][3] - mn1));
      }

      // rescale O and L
      #pragma unroll
      for (int nt = 0; nt < 8; nt++) {
        O[nt][0] *= al0; O[nt][1] *= al0;
        O[nt][2] *= al1; O[nt][3] *= al1;
      }
      Lacc[0] *= al0; Lacc[2] *= al1;

      // O += P V ; L += P * ones
      #pragma unroll
      for (int kc = 0; kc < 4; kc++) {
        const uint32_t a0 = Pp[4*kc], a1 = Pp[4*kc+1], a2 = Pp[4*kc+2], a3 = Pp[4*kc+3];
        mma_f16(Lacc, a0, a1, a2, a3, ONES_H2, ONES_H2);
        const int kc16 = kc * 16;
        #pragma unroll
        for (int np = 0; np < 4; np++) {
          uint32_t vh[4];
          const uint32_t voff = (uint32_t)(((np * 16 + b_row) * 72 + kc16 + b_col) * 2);
          ldsm4(tVh + voff, vh);
          #pragma unroll
          for (int j = 0; j < 2; j++)
            mma_f16(O[np * 2 + j], a0, a1, a2, a3, vh[2*j], vh[2*j+1]);
        }
      }
    }
    if (jb + 1 < nb) {
      cp_wait<0>(); __syncthreads();
      if (jb + 2 < nb) issue_kv(jb & 1, (jb + 2) * 128);
    }
  }

  // epilogue (Lacc cols identical -> no shuffle needed)
  const float inv0 = 1.f / Lacc[0], inv1 = 1.f / Lacc[2];
  const int colb = (bh & 15) * DH;
  const size_t orow0 = (size_t)(bh >> 4) * TT + row0g;
  const size_t orow1 = orow0 + 8;
  #pragma unroll
  for (int nd = 0; nd < 8; nd++) {
    const int d0 = nd * 8 + 2 * q;
    __half2* p0 = (__half2*)&g_Ah[orow0 * EE + colb + d0];
    __half2* p1 = (__half2*)&g_Ah[orow1 * EE + colb + d0];
    *p0 = __floats2half2_rn(O[nd][0] * inv0, O[nd][1] * inv0);
    *p1 = __floats2half2_rn(O[nd][2] * inv1, O[nd][3] * inv1);
  }
}

// ---------------------------------------------------------------------------
extern "C" void kernel_launch(void* const* d_in, const int* in_sizes, int n_in,
                              void* d_out, int out_size) {
  const float* x  = (const float*)d_in[0];
  const float* Wq = (const float*)d_in[1];
  const float* Wk = (const float*)d_in[2];
  const float* Wv = (const float*)d_in[3];
  const float* Wo = (const float*)d_in[4];
  const float* wb = (const float*)d_in[5];
  float* out = (float*)d_out;

  __half *xh, *wth, *woh, *ah;
  cudaGetSymbolAddress((void**)&xh, g_xh);
  cudaGetSymbolAddress((void**)&wth, g_Wth);
  cudaGetSymbolAddress((void**)&woh, g_Woh);
  cudaGetSymbolAddress((void**)&ah, g_Ah);

  cudaFuncSetAttribute(gemm_f16<0>, cudaFuncAttributeMaxDynamicSharedMemorySize, GEMM_SMEM);
  cudaFuncSetAttribute(gemm_f16<1>, cudaFuncAttributeMaxDynamicSharedMemorySize, GEMM_SMEM);
  cudaFuncSetAttribute(attn_f16, cudaFuncAttributeMaxDynamicSharedMemorySize, ATT_SMEM);

  prep_all<<<NB_PREP, 256>>>(x, Wo, Wq, Wk, Wv);

  gemm_f16<0><<<dim3(3*EE/128, MTOT/128), 256, GEMM_SMEM>>>(xh, wth, nullptr, nullptr);

  attn_f16<<<dim3(TT/128, BHN), 256, ATT_SMEM>>>();

  gemm_f16<1><<<dim3(EE/128, MTOT/128), 256, GEMM_SMEM>>>(ah, woh, wb, out);
}